// round 15
// baseline (speedup 1.0000x reference)
#include <cuda_runtime.h>
#include <cuda_fp16.h>
#include <math.h>

#define BB 4
#define C2 256

// ---- device-global scratch (no allocs allowed) ----
__device__ __half       g_scratch[(size_t)BB * C2 * 256 * 256]; // 134MB spectral out (fp16)
__device__ __half       g_gated[(size_t)BB * 128 * 256 * 256];  // 67MB gated (fp16)
__device__ unsigned int g_wina[256 * 64];                        // w_in as tf32 [o][c]

typedef unsigned long long u64;

// ---------- f32x2 packed helpers ----------
__device__ __forceinline__ u64 pk2(float lo, float hi) {
    u64 r;
    asm("mov.b64 %0, {%1,%2};" : "=l"(r) : "f"(lo), "f"(hi));
    return r;
}
__device__ __forceinline__ void up2(u64 v, float& lo, float& hi) {
    asm("mov.b64 {%0,%1}, %2;" : "=f"(lo), "=f"(hi) : "l"(v));
}
__device__ __forceinline__ u64 fmaf2(u64 a, u64 b, u64 c) {
    u64 d;
    asm("fma.rn.f32x2 %0, %1, %2, %3;" : "=l"(d) : "l"(a), "l"(b), "l"(c));
    return d;
}
struct PKC {
    u64 ONES, MONES, ZERO, TWO, MTWO, C2R2, M2R2, R2P, MR2P;
};
__device__ __forceinline__ u64 addp(u64 a, u64 b, const PKC& k) { return fmaf2(a, k.ONES, b); }
__device__ __forceinline__ u64 subp(u64 a, u64 b, const PKC& k) { return fmaf2(b, k.MONES, a); }
__device__ __forceinline__ u64 mulp(u64 a, u64 b, const PKC& k) { return fmaf2(a, b, k.ZERO); }

__device__ __forceinline__ unsigned int f2tf32(float v) {
    unsigned int t;
    asm("cvt.rna.tf32.f32 %0, %1;" : "=r"(t) : "f"(v));
    return t;
}

// ---------- scalar 8-point complex FFT ----------
__device__ __forceinline__ void fft8(float re[8], float im[8]) {
    const float R2 = 0.70710678118654752440f;
    float t0r = re[0] + re[4], t0i = im[0] + im[4];
    float t1r = re[0] - re[4], t1i = im[0] - im[4];
    float t2r = re[2] + re[6], t2i = im[2] + im[6];
    float t3r = re[2] - re[6], t3i = im[2] - im[6];
    float E0r = t0r + t2r, E0i = t0i + t2i;
    float E1r = t1r + t3i, E1i = t1i - t3r;
    float E2r = t0r - t2r, E2i = t0i - t2i;
    float E3r = t1r - t3i, E3i = t1i + t3r;
    float u0r = re[1] + re[5], u0i = im[1] + im[5];
    float u1r = re[1] - re[5], u1i = im[1] - im[5];
    float u2r = re[3] + re[7], u2i = im[3] + im[7];
    float u3r = re[3] - re[7], u3i = im[3] - im[7];
    float O0r = u0r + u2r, O0i = u0i + u2i;
    float O1r = u1r + u3i, O1i = u1i - u3r;
    float O2r = u0r - u2r, O2i = u0i - u2i;
    float O3r = u1r - u3i, O3i = u1i + u3r;
    float w1r = R2 * (O1r + O1i), w1i = R2 * (O1i - O1r);
    float w2r = O2i,              w2i = -O2r;
    float w3r = R2 * (O3i - O3r), w3i = -R2 * (O3r + O3i);
    re[0] = E0r + O0r; im[0] = E0i + O0i;
    re[4] = E0r - O0r; im[4] = E0i - O0i;
    re[1] = E1r + w1r; im[1] = E1i + w1i;
    re[5] = E1r - w1r; im[5] = E1i - w1i;
    re[2] = E2r + w2r; im[2] = E2i + w2i;
    re[6] = E2r - w2r; im[6] = E2i - w2i;
    re[3] = E3r + w3r; im[3] = E3i + w3i;
    re[7] = E3r - w3r; im[7] = E3i - w3i;
}

__device__ __forceinline__ void rfft8p(const u64 r[8], u64 Rr[5], u64 Ri[5], const PKC& k) {
    u64 t0 = addp(r[0], r[4], k), t1 = subp(r[0], r[4], k);
    u64 t2 = addp(r[2], r[6], k), t3 = subp(r[2], r[6], k);
    u64 E0 = addp(t0, t2, k),     E2 = subp(t0, t2, k);
    u64 u0 = addp(r[1], r[5], k), u1 = subp(r[1], r[5], k);
    u64 u2 = addp(r[3], r[7], k), u3 = subp(r[3], r[7], k);
    u64 O0 = addp(u0, u2, k),     O2 = subp(u0, u2, k);
    u64 a  = subp(u1, u3, k),     bb = addp(u1, u3, k);
    u64 w1r = mulp(a, k.R2P, k),  w1i = mulp(bb, k.MR2P, k);
    Rr[0] = addp(E0, O0, k); Ri[0] = k.ZERO;
    Rr[4] = subp(E0, O0, k); Ri[4] = k.ZERO;
    Rr[1] = addp(t1, w1r, k); Ri[1] = subp(w1i, t3, k);
    Rr[3] = subp(t1, w1r, k); Ri[3] = addp(t3, w1i, k);
    Rr[2] = E2;               Ri[2] = subp(k.ZERO, O2, k);
}

__device__ __forceinline__ void irfft8p(const u64 cr[5], const u64 ci[5], u64 o[8], const PKC& k) {
    u64 t0 = addp(cr[0], cr[4], k), t1 = subp(cr[0], cr[4], k);
    u64 E0 = fmaf2(cr[2], k.TWO, t0),  E2 = fmaf2(cr[2], k.MTWO, t0);
    u64 E1 = fmaf2(ci[2], k.MTWO, t1), E3 = fmaf2(ci[2], k.TWO, t1);
    u64 u0r = addp(cr[1], cr[3], k),   u1r = subp(cr[1], cr[3], k);
    u64 u0i = subp(ci[3], ci[1], k),   s   = addp(ci[1], ci[3], k);
    u64 O1 = subp(u1r, s, k);
    u64 O3 = addp(u1r, s, k);
    o[0] = fmaf2(u0r, k.TWO, E0);  o[4] = fmaf2(u0r, k.MTWO, E0);
    o[1] = fmaf2(O1, k.C2R2, E1);  o[5] = fmaf2(O1, k.M2R2, E1);
    o[2] = fmaf2(u0i, k.TWO, E2);  o[6] = fmaf2(u0i, k.MTWO, E2);
    o[3] = fmaf2(O3, k.M2R2, E3);  o[7] = fmaf2(O3, k.C2R2, E3);
}

// =====================================================================
// Kernel 0: weight prep — w_in as tf32 [o][c].
// =====================================================================
__global__ void k0_prep(const float* __restrict__ w_in) {
    int idx = blockIdx.x * 256 + threadIdx.x;
    if (idx < 256 * 64) g_wina[idx] = f2tf32(w_in[idx]);
}

// =====================================================================
// Kernel 1: project_in via tf32 MMA + spectral gating; fp16 output.
// =====================================================================
__global__ void __launch_bounds__(256, 2)
k1_proj_spectral(const float* __restrict__ x, const float* __restrict__ filt) {
    extern __shared__ unsigned int smu[];
    unsigned int* sB = smu;                       // [64 c][72] tf32 (18432 B)
    float* os = (float*)(smu + 64 * 72);          // [256 o][66] floats (67584 B)

    const int tid = threadIdx.x;
    const int patch = blockIdx.x;
    const int b = blockIdx.y;
    const int py = patch >> 5, px = patch & 31;

    // Stage x patch -> tf32 sB[c][p], p = j*8+i (transposed)
    {
        const float* xb = x + (size_t)b * 64 * 65536 + (size_t)py * 2048 + px * 8;
#pragma unroll
        for (int s = 0; s < 4; s++) {
            int idx = tid + s * 256;            // < 1024
            int c = idx >> 4, r = idx & 15;
            int i = r >> 1, q = r & 1;
            float4 v = *(const float4*)(xb + (size_t)c * 65536 + i * 256 + q * 4);
            unsigned int* d = sB + c * 72 + (q * 4) * 8 + i;
            d[0]  = f2tf32(v.x); d[8]  = f2tf32(v.y);
            d[16] = f2tf32(v.z); d[24] = f2tf32(v.w);
        }
    }
    __syncthreads();

    // ---------------- Phase A: tensor GEMM ----------------
    {
        const int warp = tid >> 5, lane = tid & 31;
        const int lg = lane >> 2, lt = lane & 3;

        float acc[2][8][4];
#pragma unroll
        for (int mt = 0; mt < 2; mt++)
#pragma unroll
            for (int nt = 0; nt < 8; nt++)
#pragma unroll
                for (int r = 0; r < 4; r++) acc[mt][nt][r] = 0.0f;

#pragma unroll
        for (int ks = 0; ks < 8; ks++) {
            unsigned int bf[8][2];
#pragma unroll
            for (int nt = 0; nt < 8; nt++) {
                bf[nt][0] = sB[(ks * 8 + lt) * 72 + nt * 8 + lg];
                bf[nt][1] = sB[(ks * 8 + lt + 4) * 72 + nt * 8 + lg];
            }
#pragma unroll
            for (int mt = 0; mt < 2; mt++) {
                const int row0 = warp * 32 + mt * 16 + lg;
                const int col0 = ks * 8 + lt;
                unsigned int a0 = g_wina[row0 * 64 + col0];
                unsigned int a1 = g_wina[(row0 + 8) * 64 + col0];
                unsigned int a2 = g_wina[row0 * 64 + col0 + 4];
                unsigned int a3 = g_wina[(row0 + 8) * 64 + col0 + 4];
#pragma unroll
                for (int nt = 0; nt < 8; nt++) {
                    asm volatile(
                        "mma.sync.aligned.m16n8k8.row.col.f32.tf32.tf32.f32 "
                        "{%0,%1,%2,%3}, {%4,%5,%6,%7}, {%8,%9}, {%0,%1,%2,%3};"
                        : "+f"(acc[mt][nt][0]), "+f"(acc[mt][nt][1]),
                          "+f"(acc[mt][nt][2]), "+f"(acc[mt][nt][3])
                        : "r"(a0), "r"(a1), "r"(a2), "r"(a3),
                          "r"(bf[nt][0]), "r"(bf[nt][1]));
                }
            }
        }

#pragma unroll
        for (int mt = 0; mt < 2; mt++) {
#pragma unroll
            for (int nt = 0; nt < 8; nt++) {
                int o0 = warp * 32 + mt * 16 + lg;
                int p0 = nt * 8 + lt * 2;
                *(float2*)(os + o0 * 66 + p0) =
                    make_float2(acc[mt][nt][0], acc[mt][nt][1]);
                *(float2*)(os + (o0 + 8) * 66 + p0) =
                    make_float2(acc[mt][nt][2], acc[mt][nt][3]);
            }
        }
    }
    __syncthreads();

    // ---------------- Phase B: spectral gating ----------------
    const int o = tid;
    const float R2 = 0.70710678118654752440f;
    PKC kc;
    kc.ONES = pk2(1.f, 1.f); kc.MONES = pk2(-1.f, -1.f); kc.ZERO = 0ULL;
    kc.TWO = pk2(2.f, 2.f);  kc.MTWO = pk2(-2.f, -2.f);
    kc.C2R2 = pk2(2.f * R2, 2.f * R2); kc.M2R2 = pk2(-2.f * R2, -2.f * R2);
    kc.R2P = pk2(R2, R2); kc.MR2P = pk2(-R2, -R2);

    u64* osu = (u64*)os;
    u64 acc[32];
#pragma unroll
    for (int k = 0; k < 32; k++) acc[k] = osu[o * 33 + k];

    u64 PRr[20], PRi[20];
#pragma unroll
    for (int t = 0; t < 4; t++) {
        u64 r[8];
#pragma unroll
        for (int j = 0; j < 8; j++) r[j] = acc[j * 4 + t];
        rfft8p(r, PRr + t * 5, PRi + t * 5, kc);
    }

    float Cr[40], Ci[40];
#pragma unroll
    for (int k2 = 0; k2 < 5; k2++) {
        float re[8], im[8];
#pragma unroll
        for (int t = 0; t < 4; t++) {
            up2(PRr[t * 5 + k2], re[2 * t], re[2 * t + 1]);
            up2(PRi[t * 5 + k2], im[2 * t], im[2 * t + 1]);
        }
        fft8(re, im);
#pragma unroll
        for (int k1 = 0; k1 < 8; k1++) { Cr[k1 * 5 + k2] = re[k1]; Ci[k1 * 5 + k2] = im[k1]; }
    }

    {
        const float s64 = 1.0f / 64.0f;
        const float4* fp = (const float4*)(filt + (size_t)o * 40);
#pragma unroll
        for (int q = 0; q < 10; q++) {
            float4 f = __ldg(fp + q);
            f.x *= s64; f.y *= s64; f.z *= s64; f.w *= s64;
            Cr[4 * q + 0] *= f.x; Ci[4 * q + 0] *= f.x;
            Cr[4 * q + 1] *= f.y; Ci[4 * q + 1] *= f.y;
            Cr[4 * q + 2] *= f.z; Ci[4 * q + 2] *= f.z;
            Cr[4 * q + 3] *= f.w; Ci[4 * q + 3] *= f.w;
        }
    }

#pragma unroll
    for (int k2 = 0; k2 < 5; k2++) {
        float re[8], im[8];
#pragma unroll
        for (int k1 = 0; k1 < 8; k1++) { re[k1] = Cr[k1 * 5 + k2]; im[k1] = -Ci[k1 * 5 + k2]; }
        fft8(re, im);
#pragma unroll
        for (int i = 0; i < 8; i++) { Cr[i * 5 + k2] = re[i]; Ci[i * 5 + k2] = -im[i]; }
    }

#pragma unroll
    for (int t = 0; t < 4; t++) {
        u64 cr[5], ci[5], o8[8];
#pragma unroll
        for (int k2 = 0; k2 < 5; k2++) {
            cr[k2] = pk2(Cr[(2 * t) * 5 + k2], Cr[(2 * t + 1) * 5 + k2]);
            ci[k2] = pk2(Ci[(2 * t) * 5 + k2], Ci[(2 * t + 1) * 5 + k2]);
        }
        irfft8p(cr, ci, o8, kc);
#pragma unroll
        for (int j = 0; j < 8; j++) {
            float lo, hi;
            up2(o8[j], lo, hi);
            os[o * 66 + (2 * t) * 8 + j]     = lo;
            os[o * 66 + (2 * t + 1) * 8 + j] = hi;
        }
    }

    __syncthreads();
    // Cooperative fp16 store: 4 floats -> 4 halves per u64 (8B aligned)
    {
        __half* gdst = g_scratch + (size_t)b * C2 * 65536 + (size_t)py * 2048 + px * 8;
#pragma unroll 4
        for (int s = 0; s < 16; s++) {
            int idx = tid + s * 256;           // < 4096
            int c = idx >> 4, q = idx & 15;
            int i = q >> 1, jj = (q & 1) * 4;
            float2 v0 = *(const float2*)(os + c * 66 + i * 8 + jj);
            float2 v1 = *(const float2*)(os + c * 66 + i * 8 + jj + 2);
            union { __half2 h2[2]; u64 u; } pkd;
            pkd.h2[0] = __floats2half2_rn(v0.x, v0.y);
            pkd.h2[1] = __floats2half2_rn(v1.x, v1.y);
            *(u64*)(gdst + (size_t)c * 65536 + i * 256 + jj) = pkd.u;
        }
    }
}

// =====================================================================
// Kernel 2a: depthwise 3x3 (SAME) + exact-GELU gate (fp16 in/out).
// =====================================================================
__global__ void __launch_bounds__(256)
k2a_dw_gate(const float* __restrict__ w_dw) {
    __shared__ float swdw[2304];
    __shared__ float st[2][2][34 * 36];   // [stage][x1/x2]

    const int tid = threadIdx.x;
    const int bx = blockIdx.x, by = blockIdx.y;
    const int zz = blockIdx.z;              // b*4 + cc
    const int b = zz >> 2, cc = zz & 3;

    for (int idx = tid; idx < 2304; idx += 256) swdw[idx] = w_dw[idx];

    const int lane = tid & 31, warp = tid >> 5;
    const int px2 = (tid & 15) * 2, py2 = (tid >> 4) * 2;
    const int gy0 = by * 32 - 1, gx0 = bx * 32 - 1;
    const int gx1 = gx0 + lane;
    const bool cok1 = (unsigned)gx1 < 256u;
    const int gx2 = gx0 + lane + 32;
    const bool cok2 = (lane < 2) && ((unsigned)gx2 < 256u);

    float rv1[5], rv2[5], re1[5], re2[5];
    const int ch0 = cc * 32;

#define LOADCH(CH) do { \
    const __half* p1_ = g_scratch + (size_t)(b * 256 + (CH)) * 65536; \
    const __half* p2_ = p1_ + (size_t)128 * 65536; \
    _Pragma("unroll") \
    for (int rr = 0; rr < 5; rr++) { \
        int r_ = warp + rr * 8; \
        int gy_ = gy0 + r_; \
        bool rok_ = (r_ < 34) && ((unsigned)gy_ < 256u); \
        const __half* q1_ = p1_ + (size_t)gy_ * 256; \
        const __half* q2_ = p2_ + (size_t)gy_ * 256; \
        rv1[rr] = (rok_ && cok1) ? __half2float(q1_[gx1]) : 0.f; \
        rv2[rr] = (rok_ && cok1) ? __half2float(q2_[gx1]) : 0.f; \
        re1[rr] = (rok_ && cok2) ? __half2float(q1_[gx2]) : 0.f; \
        re2[rr] = (rok_ && cok2) ? __half2float(q2_[gx2]) : 0.f; \
    } } while (0)

#define STORECH(SG) do { \
    _Pragma("unroll") \
    for (int rr = 0; rr < 5; rr++) { \
        int r_ = warp + rr * 8; \
        if (r_ < 34) { \
            st[SG][0][r_ * 36 + lane] = rv1[rr]; \
            st[SG][1][r_ * 36 + lane] = rv2[rr]; \
            if (lane < 2) { \
                st[SG][0][r_ * 36 + 32 + lane] = re1[rr]; \
                st[SG][1][r_ * 36 + 32 + lane] = re2[rr]; \
            } \
        } \
    } } while (0)

    LOADCH(ch0);
    STORECH(0);
    __syncthreads();

    for (int i = 0; i < 32; i++) {
        const int ch = ch0 + i;
        if (i + 1 < 32) LOADCH(ch + 1);   // LDGs in flight during compute below

        const float* s1 = st[i & 1][0];
        const float* s2 = st[i & 1][1];

        float wa[9], wb[9];
#pragma unroll
        for (int t = 0; t < 9; t++) { wa[t] = swdw[ch * 9 + t]; wb[t] = swdw[(ch + 128) * 9 + t]; }

        float A[4][4], Bv[4][4];
#pragma unroll
        for (int dy = 0; dy < 4; dy++) {
            float2 a0 = *(const float2*)(s1 + (py2 + dy) * 36 + px2);
            float2 a1 = *(const float2*)(s1 + (py2 + dy) * 36 + px2 + 2);
            A[dy][0] = a0.x; A[dy][1] = a0.y; A[dy][2] = a1.x; A[dy][3] = a1.y;
            float2 b0 = *(const float2*)(s2 + (py2 + dy) * 36 + px2);
            float2 b1 = *(const float2*)(s2 + (py2 + dy) * 36 + px2 + 2);
            Bv[dy][0] = b0.x; Bv[dy][1] = b0.y; Bv[dy][2] = b1.x; Bv[dy][3] = b1.y;
        }

        float g[2][2];
#pragma unroll
        for (int oy = 0; oy < 2; oy++) {
#pragma unroll
            for (int ox = 0; ox < 2; ox++) {
                float d1 = 0.f, d2 = 0.f;
#pragma unroll
                for (int ky = 0; ky < 3; ky++)
#pragma unroll
                    for (int kx = 0; kx < 3; kx++) {
                        d1 = fmaf(wa[ky * 3 + kx], A[oy + ky][ox + kx], d1);
                        d2 = fmaf(wb[ky * 3 + kx], Bv[oy + ky][ox + kx], d2);
                    }
                g[oy][ox] = 0.5f * d1 * (1.0f + erff(d1 * 0.70710678118654752f)) * d2;
            }
        }

        __half* go = g_gated + (size_t)(b * 128 + ch) * 65536;
        const int oy0 = by * 32 + py2, ox0 = bx * 32 + px2;
        *(__half2*)(go + (size_t)oy0 * 256 + ox0)       = __floats2half2_rn(g[0][0], g[0][1]);
        *(__half2*)(go + (size_t)(oy0 + 1) * 256 + ox0) = __floats2half2_rn(g[1][0], g[1][1]);

        if (i + 1 < 32) STORECH((i + 1) & 1);   // waits on LDGs, fills other stage
        __syncthreads();
    }
#undef LOADCH
#undef STORECH
}

// =====================================================================
// Kernel 2b: project_out via tf32 mma.sync (fp16 input staging).
// =====================================================================
__global__ void __launch_bounds__(256, 2)
k2b_proj_out_tf32(const float* __restrict__ w_out, float* __restrict__ out) {
    extern __shared__ unsigned int smu[];
    unsigned int* sW = smu;                 // [64][132] tf32 (33792 B)
    unsigned int* sG = smu + 64 * 132;      // [16][260] tf32 (16640 B)

    const int tid = threadIdx.x;
    const int y = blockIdx.x, b = blockIdx.y;
    const int warp = tid >> 5, lane = tid & 31;
    const int lg = lane >> 2;      // groupID 0..7
    const int lt = lane & 3;       // thread-in-group 0..3

    for (int i = tid; i < 8192; i += 256) {
        int o = i >> 7, k = i & 127;
        sW[o * 132 + k] = f2tf32(w_out[i]);
    }

    float acc[4][4][4];
#pragma unroll
    for (int mt = 0; mt < 4; mt++)
#pragma unroll
        for (int nt = 0; nt < 4; nt++)
#pragma unroll
            for (int r = 0; r < 4; r++) acc[mt][nt][r] = 0.0f;

    const __half* gbase = g_gated + (size_t)b * 128 * 65536 + (size_t)y * 256;

    for (int kb = 0; kb < 8; kb++) {
        __syncthreads();
        // Stage G chunk [16 k][256 px]: 8 halves per uint4 -> tf32
#pragma unroll
        for (int s = 0; s < 2; s++) {
            int i = tid + s * 256;              // < 512
            int kl = i >> 5, q8 = (i & 31) * 8;
            uint4 v = *(const uint4*)(gbase + (size_t)(kb * 16 + kl) * 65536 + q8);
            const __half2* hp = (const __half2*)&v;
            unsigned int* d = sG + kl * 260 + q8;
#pragma unroll
            for (int t = 0; t < 4; t++) {
                float2 f = __half22float2(hp[t]);
                d[2 * t]     = f2tf32(f.x);
                d[2 * t + 1] = f2tf32(f.y);
            }
        }
        __syncthreads();

#pragma unroll
        for (int ks = 0; ks < 2; ks++) {
            const int k0 = kb * 16 + ks * 8;
            const int kl0 = ks * 8;
            unsigned int bf[4][2];
#pragma unroll
            for (int nt = 0; nt < 4; nt++) {
                int n0 = warp * 32 + nt * 8 + lg;
                bf[nt][0] = sG[(kl0 + lt) * 260 + n0];
                bf[nt][1] = sG[(kl0 + lt + 4) * 260 + n0];
            }
#pragma unroll
            for (int mt = 0; mt < 4; mt++) {
                const int row0 = mt * 16 + lg;
                const int col0 = k0 + lt;
                unsigned int a0 = sW[row0 * 132 + col0];
                unsigned int a1 = sW[(row0 + 8) * 132 + col0];
                unsigned int a2 = sW[row0 * 132 + col0 + 4];
                unsigned int a3 = sW[(row0 + 8) * 132 + col0 + 4];
#pragma unroll
                for (int nt = 0; nt < 4; nt++) {
                    asm volatile(
                        "mma.sync.aligned.m16n8k8.row.col.f32.tf32.tf32.f32 "
                        "{%0,%1,%2,%3}, {%4,%5,%6,%7}, {%8,%9}, {%0,%1,%2,%3};"
                        : "+f"(acc[mt][nt][0]), "+f"(acc[mt][nt][1]),
                          "+f"(acc[mt][nt][2]), "+f"(acc[mt][nt][3])
                        : "r"(a0), "r"(a1), "r"(a2), "r"(a3),
                          "r"(bf[nt][0]), "r"(bf[nt][1]));
                }
            }
        }
    }

#pragma unroll
    for (int mt = 0; mt < 4; mt++) {
#pragma unroll
        for (int nt = 0; nt < 4; nt++) {
            int o0 = mt * 16 + lg;
            int px = warp * 32 + nt * 8 + lt * 2;
            float* base0 = out + ((size_t)(b * 64 + o0) * 256 + y) * 256 + px;
            *(float2*)base0 = make_float2(acc[mt][nt][0], acc[mt][nt][1]);
            float* base1 = out + ((size_t)(b * 64 + o0 + 8) * 256 + y) * 256 + px;
            *(float2*)base1 = make_float2(acc[mt][nt][2], acc[mt][nt][3]);
        }
    }
}

extern "C" void kernel_launch(void* const* d_in, const int* in_sizes, int n_in,
                              void* d_out, int out_size) {
    (void)in_sizes; (void)n_in; (void)out_size;
    const float* x     = (const float*)d_in[0];
    const float* w_in  = (const float*)d_in[1];
    const float* w_dw  = (const float*)d_in[2];
    const float* filt  = (const float*)d_in[3];
    const float* w_out = (const float*)d_in[4];
    float* out = (float*)d_out;

    const int sm1  = 64 * 72 * 4 + 256 * 66 * 4;                    // 86016 B
    const int sm2b = (64 * 132 + 16 * 260) * (int)sizeof(unsigned); // 50432 B
    cudaFuncSetAttribute(k1_proj_spectral,  cudaFuncAttributeMaxDynamicSharedMemorySize, sm1);
    cudaFuncSetAttribute(k2b_proj_out_tf32, cudaFuncAttributeMaxDynamicSharedMemorySize, sm2b);

    k0_prep<<<64, 256>>>(w_in);
    k1_proj_spectral<<<dim3(1024, 4, 1), 256, sm1>>>(x, filt);
    k2a_dw_gate<<<dim3(8, 8, 16), 256>>>(w_dw);
    k2b_proj_out_tf32<<<dim3(256, 4, 1), 256, sm2b>>>(w_out, out);
}

// round 16
// speedup vs baseline: 1.1964x; 1.1964x over previous
#include <cuda_runtime.h>
#include <cuda_fp16.h>
#include <math.h>

#define BB 4
#define C2 256

// ---- device-global scratch (no allocs allowed) ----
__device__ float        g_scratch[(size_t)BB * C2 * 256 * 256]; // 268MB spectral out (fp32)
__device__ __half       g_gated[(size_t)BB * 128 * 256 * 256];  // 67MB gated (fp16)
__device__ unsigned int g_wina[256 * 64];                        // w_in as tf32 [o][c]

typedef unsigned long long u64;

// ---------- f32x2 packed helpers ----------
__device__ __forceinline__ u64 pk2(float lo, float hi) {
    u64 r;
    asm("mov.b64 %0, {%1,%2};" : "=l"(r) : "f"(lo), "f"(hi));
    return r;
}
__device__ __forceinline__ void up2(u64 v, float& lo, float& hi) {
    asm("mov.b64 {%0,%1}, %2;" : "=f"(lo), "=f"(hi) : "l"(v));
}
__device__ __forceinline__ u64 fmaf2(u64 a, u64 b, u64 c) {
    u64 d;
    asm("fma.rn.f32x2 %0, %1, %2, %3;" : "=l"(d) : "l"(a), "l"(b), "l"(c));
    return d;
}
struct PKC {
    u64 ONES, MONES, ZERO, TWO, MTWO, C2R2, M2R2, R2P, MR2P;
};
__device__ __forceinline__ u64 addp(u64 a, u64 b, const PKC& k) { return fmaf2(a, k.ONES, b); }
__device__ __forceinline__ u64 subp(u64 a, u64 b, const PKC& k) { return fmaf2(b, k.MONES, a); }
__device__ __forceinline__ u64 mulp(u64 a, u64 b, const PKC& k) { return fmaf2(a, b, k.ZERO); }

__device__ __forceinline__ unsigned int f2tf32(float v) {
    unsigned int t;
    asm("cvt.rna.tf32.f32 %0, %1;" : "=r"(t) : "f"(v));
    return t;
}

// ---------- scalar 8-point complex FFT ----------
__device__ __forceinline__ void fft8(float re[8], float im[8]) {
    const float R2 = 0.70710678118654752440f;
    float t0r = re[0] + re[4], t0i = im[0] + im[4];
    float t1r = re[0] - re[4], t1i = im[0] - im[4];
    float t2r = re[2] + re[6], t2i = im[2] + im[6];
    float t3r = re[2] - re[6], t3i = im[2] - im[6];
    float E0r = t0r + t2r, E0i = t0i + t2i;
    float E1r = t1r + t3i, E1i = t1i - t3r;
    float E2r = t0r - t2r, E2i = t0i - t2i;
    float E3r = t1r - t3i, E3i = t1i + t3r;
    float u0r = re[1] + re[5], u0i = im[1] + im[5];
    float u1r = re[1] - re[5], u1i = im[1] - im[5];
    float u2r = re[3] + re[7], u2i = im[3] + im[7];
    float u3r = re[3] - re[7], u3i = im[3] - im[7];
    float O0r = u0r + u2r, O0i = u0i + u2i;
    float O1r = u1r + u3i, O1i = u1i - u3r;
    float O2r = u0r - u2r, O2i = u0i - u2i;
    float O3r = u1r - u3i, O3i = u1i + u3r;
    float w1r = R2 * (O1r + O1i), w1i = R2 * (O1i - O1r);
    float w2r = O2i,              w2i = -O2r;
    float w3r = R2 * (O3i - O3r), w3i = -R2 * (O3r + O3i);
    re[0] = E0r + O0r; im[0] = E0i + O0i;
    re[4] = E0r - O0r; im[4] = E0i - O0i;
    re[1] = E1r + w1r; im[1] = E1i + w1i;
    re[5] = E1r - w1r; im[5] = E1i - w1i;
    re[2] = E2r + w2r; im[2] = E2i + w2i;
    re[6] = E2r - w2r; im[6] = E2i - w2i;
    re[3] = E3r + w3r; im[3] = E3i + w3i;
    re[7] = E3r - w3r; im[7] = E3i - w3i;
}

__device__ __forceinline__ void rfft8p(const u64 r[8], u64 Rr[5], u64 Ri[5], const PKC& k) {
    u64 t0 = addp(r[0], r[4], k), t1 = subp(r[0], r[4], k);
    u64 t2 = addp(r[2], r[6], k), t3 = subp(r[2], r[6], k);
    u64 E0 = addp(t0, t2, k),     E2 = subp(t0, t2, k);
    u64 u0 = addp(r[1], r[5], k), u1 = subp(r[1], r[5], k);
    u64 u2 = addp(r[3], r[7], k), u3 = subp(r[3], r[7], k);
    u64 O0 = addp(u0, u2, k),     O2 = subp(u0, u2, k);
    u64 a  = subp(u1, u3, k),     bb = addp(u1, u3, k);
    u64 w1r = mulp(a, k.R2P, k),  w1i = mulp(bb, k.MR2P, k);
    Rr[0] = addp(E0, O0, k); Ri[0] = k.ZERO;
    Rr[4] = subp(E0, O0, k); Ri[4] = k.ZERO;
    Rr[1] = addp(t1, w1r, k); Ri[1] = subp(w1i, t3, k);
    Rr[3] = subp(t1, w1r, k); Ri[3] = addp(t3, w1i, k);
    Rr[2] = E2;               Ri[2] = subp(k.ZERO, O2, k);
}

__device__ __forceinline__ void irfft8p(const u64 cr[5], const u64 ci[5], u64 o[8], const PKC& k) {
    u64 t0 = addp(cr[0], cr[4], k), t1 = subp(cr[0], cr[4], k);
    u64 E0 = fmaf2(cr[2], k.TWO, t0),  E2 = fmaf2(cr[2], k.MTWO, t0);
    u64 E1 = fmaf2(ci[2], k.MTWO, t1), E3 = fmaf2(ci[2], k.TWO, t1);
    u64 u0r = addp(cr[1], cr[3], k),   u1r = subp(cr[1], cr[3], k);
    u64 u0i = subp(ci[3], ci[1], k),   s   = addp(ci[1], ci[3], k);
    u64 O1 = subp(u1r, s, k);
    u64 O3 = addp(u1r, s, k);
    o[0] = fmaf2(u0r, k.TWO, E0);  o[4] = fmaf2(u0r, k.MTWO, E0);
    o[1] = fmaf2(O1, k.C2R2, E1);  o[5] = fmaf2(O1, k.M2R2, E1);
    o[2] = fmaf2(u0i, k.TWO, E2);  o[6] = fmaf2(u0i, k.MTWO, E2);
    o[3] = fmaf2(O3, k.M2R2, E3);  o[7] = fmaf2(O3, k.C2R2, E3);
}

// =====================================================================
// Kernel 0: weight prep — w_in as tf32 [o][c].
// =====================================================================
__global__ void k0_prep(const float* __restrict__ w_in) {
    int idx = blockIdx.x * 256 + threadIdx.x;
    if (idx < 256 * 64) g_wina[idx] = f2tf32(w_in[idx]);
}

// =====================================================================
// Kernel 1: project_in via tf32 MMA + spectral gating (R13-measured form,
// fp32 output to g_scratch).
// =====================================================================
__global__ void __launch_bounds__(256, 2)
k1_proj_spectral(const float* __restrict__ x, const float* __restrict__ filt) {
    extern __shared__ unsigned int smu[];
    unsigned int* sB = smu;                       // [64 c][72] tf32 (18432 B)
    float* os = (float*)(smu + 64 * 72);          // [256 o][66] floats (67584 B)

    const int tid = threadIdx.x;
    const int patch = blockIdx.x;
    const int b = blockIdx.y;
    const int py = patch >> 5, px = patch & 31;

    // Stage x patch -> tf32 sB[c][p], p = j*8+i (transposed)
    {
        const float* xb = x + (size_t)b * 64 * 65536 + (size_t)py * 2048 + px * 8;
#pragma unroll
        for (int s = 0; s < 4; s++) {
            int idx = tid + s * 256;            // < 1024
            int c = idx >> 4, r = idx & 15;
            int i = r >> 1, q = r & 1;
            float4 v = *(const float4*)(xb + (size_t)c * 65536 + i * 256 + q * 4);
            unsigned int* d = sB + c * 72 + (q * 4) * 8 + i;
            d[0]  = f2tf32(v.x); d[8]  = f2tf32(v.y);
            d[16] = f2tf32(v.z); d[24] = f2tf32(v.w);
        }
    }
    __syncthreads();

    // ---------------- Phase A: tensor GEMM ----------------
    {
        const int warp = tid >> 5, lane = tid & 31;
        const int lg = lane >> 2, lt = lane & 3;

        float acc[2][8][4];
#pragma unroll
        for (int mt = 0; mt < 2; mt++)
#pragma unroll
            for (int nt = 0; nt < 8; nt++)
#pragma unroll
                for (int r = 0; r < 4; r++) acc[mt][nt][r] = 0.0f;

#pragma unroll
        for (int ks = 0; ks < 8; ks++) {
            unsigned int bf[8][2];
#pragma unroll
            for (int nt = 0; nt < 8; nt++) {
                bf[nt][0] = sB[(ks * 8 + lt) * 72 + nt * 8 + lg];
                bf[nt][1] = sB[(ks * 8 + lt + 4) * 72 + nt * 8 + lg];
            }
#pragma unroll
            for (int mt = 0; mt < 2; mt++) {
                const int row0 = warp * 32 + mt * 16 + lg;
                const int col0 = ks * 8 + lt;
                unsigned int a0 = g_wina[row0 * 64 + col0];
                unsigned int a1 = g_wina[(row0 + 8) * 64 + col0];
                unsigned int a2 = g_wina[row0 * 64 + col0 + 4];
                unsigned int a3 = g_wina[(row0 + 8) * 64 + col0 + 4];
#pragma unroll
                for (int nt = 0; nt < 8; nt++) {
                    asm volatile(
                        "mma.sync.aligned.m16n8k8.row.col.f32.tf32.tf32.f32 "
                        "{%0,%1,%2,%3}, {%4,%5,%6,%7}, {%8,%9}, {%0,%1,%2,%3};"
                        : "+f"(acc[mt][nt][0]), "+f"(acc[mt][nt][1]),
                          "+f"(acc[mt][nt][2]), "+f"(acc[mt][nt][3])
                        : "r"(a0), "r"(a1), "r"(a2), "r"(a3),
                          "r"(bf[nt][0]), "r"(bf[nt][1]));
                }
            }
        }

#pragma unroll
        for (int mt = 0; mt < 2; mt++) {
#pragma unroll
            for (int nt = 0; nt < 8; nt++) {
                int o0 = warp * 32 + mt * 16 + lg;
                int p0 = nt * 8 + lt * 2;
                *(float2*)(os + o0 * 66 + p0) =
                    make_float2(acc[mt][nt][0], acc[mt][nt][1]);
                *(float2*)(os + (o0 + 8) * 66 + p0) =
                    make_float2(acc[mt][nt][2], acc[mt][nt][3]);
            }
        }
    }
    __syncthreads();

    // ---------------- Phase B: spectral gating ----------------
    const int o = tid;
    const float R2 = 0.70710678118654752440f;
    PKC kc;
    kc.ONES = pk2(1.f, 1.f); kc.MONES = pk2(-1.f, -1.f); kc.ZERO = 0ULL;
    kc.TWO = pk2(2.f, 2.f);  kc.MTWO = pk2(-2.f, -2.f);
    kc.C2R2 = pk2(2.f * R2, 2.f * R2); kc.M2R2 = pk2(-2.f * R2, -2.f * R2);
    kc.R2P = pk2(R2, R2); kc.MR2P = pk2(-R2, -R2);

    u64* osu = (u64*)os;
    u64 acc[32];
#pragma unroll
    for (int k = 0; k < 32; k++) acc[k] = osu[o * 33 + k];

    u64 PRr[20], PRi[20];
#pragma unroll
    for (int t = 0; t < 4; t++) {
        u64 r[8];
#pragma unroll
        for (int j = 0; j < 8; j++) r[j] = acc[j * 4 + t];
        rfft8p(r, PRr + t * 5, PRi + t * 5, kc);
    }

    float Cr[40], Ci[40];
#pragma unroll
    for (int k2 = 0; k2 < 5; k2++) {
        float re[8], im[8];
#pragma unroll
        for (int t = 0; t < 4; t++) {
            up2(PRr[t * 5 + k2], re[2 * t], re[2 * t + 1]);
            up2(PRi[t * 5 + k2], im[2 * t], im[2 * t + 1]);
        }
        fft8(re, im);
#pragma unroll
        for (int k1 = 0; k1 < 8; k1++) { Cr[k1 * 5 + k2] = re[k1]; Ci[k1 * 5 + k2] = im[k1]; }
    }

    {
        const float s64 = 1.0f / 64.0f;
        const float4* fp = (const float4*)(filt + (size_t)o * 40);
#pragma unroll
        for (int q = 0; q < 10; q++) {
            float4 f = __ldg(fp + q);
            f.x *= s64; f.y *= s64; f.z *= s64; f.w *= s64;
            Cr[4 * q + 0] *= f.x; Ci[4 * q + 0] *= f.x;
            Cr[4 * q + 1] *= f.y; Ci[4 * q + 1] *= f.y;
            Cr[4 * q + 2] *= f.z; Ci[4 * q + 2] *= f.z;
            Cr[4 * q + 3] *= f.w; Ci[4 * q + 3] *= f.w;
        }
    }

#pragma unroll
    for (int k2 = 0; k2 < 5; k2++) {
        float re[8], im[8];
#pragma unroll
        for (int k1 = 0; k1 < 8; k1++) { re[k1] = Cr[k1 * 5 + k2]; im[k1] = -Ci[k1 * 5 + k2]; }
        fft8(re, im);
#pragma unroll
        for (int i = 0; i < 8; i++) { Cr[i * 5 + k2] = re[i]; Ci[i * 5 + k2] = -im[i]; }
    }

#pragma unroll
    for (int t = 0; t < 4; t++) {
        u64 cr[5], ci[5], o8[8];
#pragma unroll
        for (int k2 = 0; k2 < 5; k2++) {
            cr[k2] = pk2(Cr[(2 * t) * 5 + k2], Cr[(2 * t + 1) * 5 + k2]);
            ci[k2] = pk2(Ci[(2 * t) * 5 + k2], Ci[(2 * t + 1) * 5 + k2]);
        }
        irfft8p(cr, ci, o8, kc);
#pragma unroll
        for (int j = 0; j < 8; j++) {
            float lo, hi;
            up2(o8[j], lo, hi);
            os[o * 66 + (2 * t) * 8 + j]     = lo;
            os[o * 66 + (2 * t + 1) * 8 + j] = hi;
        }
    }

    __syncthreads();
    // Cooperative u64 fp32 store (R13-measured pattern, conflict-free)
    {
        const u64* osrc = (const u64*)os;  // 33 u64 per ch
        float* gdst = g_scratch + (size_t)b * C2 * 65536 + (size_t)py * 2048 + px * 8;
#pragma unroll 4
        for (int s = 0; s < 32; s++) {
            int idx = tid + s * 256;           // < 8192
            int c = idx >> 5, t = idx & 31;
            int i = t >> 2, jj = t & 3;
            *(u64*)(gdst + (size_t)c * 65536 + i * 256 + jj * 2) = osrc[c * 33 + t];
        }
    }
}

// =====================================================================
// Kernel 2a: depthwise 3x3 (SAME) + exact-GELU gate.
// fp32 loads from g_scratch (R13 form), fp16 stores to g_gated.
// =====================================================================
__global__ void __launch_bounds__(256)
k2a_dw_gate(const float* __restrict__ w_dw) {
    __shared__ float swdw[2304];
    __shared__ float st[2][2][34 * 36];   // [stage][x1/x2]

    const int tid = threadIdx.x;
    const int bx = blockIdx.x, by = blockIdx.y;
    const int zz = blockIdx.z;              // b*4 + cc
    const int b = zz >> 2, cc = zz & 3;

    for (int idx = tid; idx < 2304; idx += 256) swdw[idx] = w_dw[idx];

    const int lane = tid & 31, warp = tid >> 5;
    const int px2 = (tid & 15) * 2, py2 = (tid >> 4) * 2;
    const int gy0 = by * 32 - 1, gx0 = bx * 32 - 1;
    const int gx1 = gx0 + lane;
    const bool cok1 = (unsigned)gx1 < 256u;
    const int gx2 = gx0 + lane + 32;
    const bool cok2 = (lane < 2) && ((unsigned)gx2 < 256u);

    float rv1[5], rv2[5], re1[5], re2[5];
    const int ch0 = cc * 32;

#define LOADCH(CH) do { \
    const float* p1_ = g_scratch + (size_t)(b * 256 + (CH)) * 65536; \
    const float* p2_ = p1_ + (size_t)128 * 65536; \
    _Pragma("unroll") \
    for (int rr = 0; rr < 5; rr++) { \
        int r_ = warp + rr * 8; \
        int gy_ = gy0 + r_; \
        bool rok_ = (r_ < 34) && ((unsigned)gy_ < 256u); \
        const float* q1_ = p1_ + (size_t)gy_ * 256; \
        const float* q2_ = p2_ + (size_t)gy_ * 256; \
        rv1[rr] = (rok_ && cok1) ? q1_[gx1] : 0.f; \
        rv2[rr] = (rok_ && cok1) ? q2_[gx1] : 0.f; \
        re1[rr] = (rok_ && cok2) ? q1_[gx2] : 0.f; \
        re2[rr] = (rok_ && cok2) ? q2_[gx2] : 0.f; \
    } } while (0)

#define STORECH(SG) do { \
    _Pragma("unroll") \
    for (int rr = 0; rr < 5; rr++) { \
        int r_ = warp + rr * 8; \
        if (r_ < 34) { \
            st[SG][0][r_ * 36 + lane] = rv1[rr]; \
            st[SG][1][r_ * 36 + lane] = rv2[rr]; \
            if (lane < 2) { \
                st[SG][0][r_ * 36 + 32 + lane] = re1[rr]; \
                st[SG][1][r_ * 36 + 32 + lane] = re2[rr]; \
            } \
        } \
    } } while (0)

    LOADCH(ch0);
    STORECH(0);
    __syncthreads();

    for (int i = 0; i < 32; i++) {
        const int ch = ch0 + i;
        if (i + 1 < 32) LOADCH(ch + 1);   // LDGs in flight during compute below

        const float* s1 = st[i & 1][0];
        const float* s2 = st[i & 1][1];

        float wa[9], wb[9];
#pragma unroll
        for (int t = 0; t < 9; t++) { wa[t] = swdw[ch * 9 + t]; wb[t] = swdw[(ch + 128) * 9 + t]; }

        float A[4][4], Bv[4][4];
#pragma unroll
        for (int dy = 0; dy < 4; dy++) {
            float2 a0 = *(const float2*)(s1 + (py2 + dy) * 36 + px2);
            float2 a1 = *(const float2*)(s1 + (py2 + dy) * 36 + px2 + 2);
            A[dy][0] = a0.x; A[dy][1] = a0.y; A[dy][2] = a1.x; A[dy][3] = a1.y;
            float2 b0 = *(const float2*)(s2 + (py2 + dy) * 36 + px2);
            float2 b1 = *(const float2*)(s2 + (py2 + dy) * 36 + px2 + 2);
            Bv[dy][0] = b0.x; Bv[dy][1] = b0.y; Bv[dy][2] = b1.x; Bv[dy][3] = b1.y;
        }

        float g[2][2];
#pragma unroll
        for (int oy = 0; oy < 2; oy++) {
#pragma unroll
            for (int ox = 0; ox < 2; ox++) {
                float d1 = 0.f, d2 = 0.f;
#pragma unroll
                for (int ky = 0; ky < 3; ky++)
#pragma unroll
                    for (int kx = 0; kx < 3; kx++) {
                        d1 = fmaf(wa[ky * 3 + kx], A[oy + ky][ox + kx], d1);
                        d2 = fmaf(wb[ky * 3 + kx], Bv[oy + ky][ox + kx], d2);
                    }
                g[oy][ox] = 0.5f * d1 * (1.0f + erff(d1 * 0.70710678118654752f)) * d2;
            }
        }

        __half* go = g_gated + (size_t)(b * 128 + ch) * 65536;
        const int oy0 = by * 32 + py2, ox0 = bx * 32 + px2;
        *(__half2*)(go + (size_t)oy0 * 256 + ox0)       = __floats2half2_rn(g[0][0], g[0][1]);
        *(__half2*)(go + (size_t)(oy0 + 1) * 256 + ox0) = __floats2half2_rn(g[1][0], g[1][1]);

        if (i + 1 < 32) STORECH((i + 1) & 1);   // waits on LDGs, fills other stage
        __syncthreads();
    }
#undef LOADCH
#undef STORECH
}

// =====================================================================
// Kernel 2b: project_out via tf32 mma.sync (fp16 input staging — measured
// 64.4us in R14).
// =====================================================================
__global__ void __launch_bounds__(256, 2)
k2b_proj_out_tf32(const float* __restrict__ w_out, float* __restrict__ out) {
    extern __shared__ unsigned int smu[];
    unsigned int* sW = smu;                 // [64][132] tf32 (33792 B)
    unsigned int* sG = smu + 64 * 132;      // [16][260] tf32 (16640 B)

    const int tid = threadIdx.x;
    const int y = blockIdx.x, b = blockIdx.y;
    const int warp = tid >> 5, lane = tid & 31;
    const int lg = lane >> 2;      // groupID 0..7
    const int lt = lane & 3;       // thread-in-group 0..3

    for (int i = tid; i < 8192; i += 256) {
        int o = i >> 7, k = i & 127;
        sW[o * 132 + k] = f2tf32(w_out[i]);
    }

    float acc[4][4][4];
#pragma unroll
    for (int mt = 0; mt < 4; mt++)
#pragma unroll
        for (int nt = 0; nt < 4; nt++)
#pragma unroll
            for (int r = 0; r < 4; r++) acc[mt][nt][r] = 0.0f;

    const __half* gbase = g_gated + (size_t)b * 128 * 65536 + (size_t)y * 256;

    for (int kb = 0; kb < 8; kb++) {
        __syncthreads();
        // Stage G chunk [16 k][256 px]: 8 halves per uint4 -> tf32
#pragma unroll
        for (int s = 0; s < 2; s++) {
            int i = tid + s * 256;              // < 512
            int kl = i >> 5, q8 = (i & 31) * 8;
            uint4 v = *(const uint4*)(gbase + (size_t)(kb * 16 + kl) * 65536 + q8);
            const __half2* hp = (const __half2*)&v;
            unsigned int* d = sG + kl * 260 + q8;
#pragma unroll
            for (int t = 0; t < 4; t++) {
                float2 f = __half22float2(hp[t]);
                d[2 * t]     = f2tf32(f.x);
                d[2 * t + 1] = f2tf32(f.y);
            }
        }
        __syncthreads();

#pragma unroll
        for (int ks = 0; ks < 2; ks++) {
            const int k0 = kb * 16 + ks * 8;
            const int kl0 = ks * 8;
            unsigned int bf[4][2];
#pragma unroll
            for (int nt = 0; nt < 4; nt++) {
                int n0 = warp * 32 + nt * 8 + lg;
                bf[nt][0] = sG[(kl0 + lt) * 260 + n0];
                bf[nt][1] = sG[(kl0 + lt + 4) * 260 + n0];
            }
#pragma unroll
            for (int mt = 0; mt < 4; mt++) {
                const int row0 = mt * 16 + lg;
                const int col0 = k0 + lt;
                unsigned int a0 = sW[row0 * 132 + col0];
                unsigned int a1 = sW[(row0 + 8) * 132 + col0];
                unsigned int a2 = sW[row0 * 132 + col0 + 4];
                unsigned int a3 = sW[(row0 + 8) * 132 + col0 + 4];
#pragma unroll
                for (int nt = 0; nt < 4; nt++) {
                    asm volatile(
                        "mma.sync.aligned.m16n8k8.row.col.f32.tf32.tf32.f32 "
                        "{%0,%1,%2,%3}, {%4,%5,%6,%7}, {%8,%9}, {%0,%1,%2,%3};"
                        : "+f"(acc[mt][nt][0]), "+f"(acc[mt][nt][1]),
                          "+f"(acc[mt][nt][2]), "+f"(acc[mt][nt][3])
                        : "r"(a0), "r"(a1), "r"(a2), "r"(a3),
                          "r"(bf[nt][0]), "r"(bf[nt][1]));
                }
            }
        }
    }

#pragma unroll
    for (int mt = 0; mt < 4; mt++) {
#pragma unroll
        for (int nt = 0; nt < 4; nt++) {
            int o0 = mt * 16 + lg;
            int px = warp * 32 + nt * 8 + lt * 2;
            float* base0 = out + ((size_t)(b * 64 + o0) * 256 + y) * 256 + px;
            *(float2*)base0 = make_float2(acc[mt][nt][0], acc[mt][nt][1]);
            float* base1 = out + ((size_t)(b * 64 + o0 + 8) * 256 + y) * 256 + px;
            *(float2*)base1 = make_float2(acc[mt][nt][2], acc[mt][nt][3]);
        }
    }
}

extern "C" void kernel_launch(void* const* d_in, const int* in_sizes, int n_in,
                              void* d_out, int out_size) {
    (void)in_sizes; (void)n_in; (void)out_size;
    const float* x     = (const float*)d_in[0];
    const float* w_in  = (const float*)d_in[1];
    const float* w_dw  = (const float*)d_in[2];
    const float* filt  = (const float*)d_in[3];
    const float* w_out = (const float*)d_in[4];
    float* out = (float*)d_out;

    const int sm1  = 64 * 72 * 4 + 256 * 66 * 4;                    // 86016 B
    const int sm2b = (64 * 132 + 16 * 260) * (int)sizeof(unsigned); // 50432 B
    cudaFuncSetAttribute(k1_proj_spectral,  cudaFuncAttributeMaxDynamicSharedMemorySize, sm1);
    cudaFuncSetAttribute(k2b_proj_out_tf32, cudaFuncAttributeMaxDynamicSharedMemorySize, sm2b);

    k0_prep<<<64, 256>>>(w_in);
    k1_proj_spectral<<<dim3(1024, 4, 1), 256, sm1>>>(x, filt);
    k2a_dw_gate<<<dim3(8, 8, 16), 256>>>(w_dw);
    k2b_proj_out_tf32<<<dim3(256, 4, 1), 256, sm2b>>>(w_out, out);
}